// round 14
// baseline (speedup 1.0000x reference)
#include <cuda_runtime.h>
#include <cuda_fp16.h>
#include <cstdint>
#include <math.h>

// FLC pooling, fused, circulant-strip + pipelined-load edition. 1 CTA = 1 image.
//   Conv[h][n] = sum_j x[h][2j+1] * R[n][j]   (R circulant -> 448B strip)
//   To[j][n]  = 0.5*x[2j+1][2n] + Conv[2j+1][n]   (stored reversed, full T odd rows)
//   Tec[q][n] = Conv[2q][n]                        (diagonal deferred to stage2)
//   out[m][n] = 0.25*x[2m][2n] + 0.5*Tec[m][n] + sum_j R[m][j] To[j][n]
//               - (-1)^(m+n) * C_img / 224^2
// A double-buffered: half-1 x-load is software-pipelined inside half-0's GEMM.

#define HO   112
#define NIMG 1024
#define PADB 240          // smem row stride bytes -> conflict-free ldmatrix

__device__ __half g_strip[448];   // [0..223]=v2[t]; [224+i]=v2[i+1] (parity copy)

// ------------------------------------------------------------------ helpers
__device__ __forceinline__ uint32_t smem_u32(const void* p) {
    uint32_t a;
    asm("{ .reg .u64 t; cvta.to.shared.u64 t, %1; cvt.u32.u64 %0, t; }"
        : "=r"(a) : "l"(p));
    return a;
}
__device__ __forceinline__ void ldx4(uint32_t r[4], uint32_t a) {
    asm volatile("ldmatrix.sync.aligned.m8n8.x4.shared.b16 {%0,%1,%2,%3}, [%4];"
                 : "=r"(r[0]), "=r"(r[1]), "=r"(r[2]), "=r"(r[3]) : "r"(a));
}
__device__ __forceinline__ void ldx4t(uint32_t r[4], uint32_t a) {
    asm volatile("ldmatrix.sync.aligned.m8n8.x4.trans.shared.b16 {%0,%1,%2,%3}, [%4];"
                 : "=r"(r[0]), "=r"(r[1]), "=r"(r[2]), "=r"(r[3]) : "r"(a));
}
__device__ __forceinline__ void ldx2t(uint32_t r[2], uint32_t a) {
    asm volatile("ldmatrix.sync.aligned.m8n8.x2.trans.shared.b16 {%0,%1}, [%2];"
                 : "=r"(r[0]), "=r"(r[1]) : "r"(a));
}
__device__ __forceinline__ void mma16816(float c[4], const uint32_t a[4],
                                         uint32_t b0, uint32_t b1) {
    asm volatile(
        "mma.sync.aligned.m16n8k16.row.col.f32.f16.f16.f32 "
        "{%0,%1,%2,%3}, {%4,%5,%6,%7}, {%8,%9}, {%0,%1,%2,%3};"
        : "+f"(c[0]), "+f"(c[1]), "+f"(c[2]), "+f"(c[3])
        : "r"(a[0]), "r"(a[1]), "r"(a[2]), "r"(a[3]), "r"(b0), "r"(b1));
}
__device__ __forceinline__ uint32_t pk2(float a, float b) {
    __half2 h = __floats2half2_rn(a, b);
    return *reinterpret_cast<uint32_t*>(&h);
}
__device__ __forceinline__ void sts64(uint32_t a, uint32_t x, uint32_t y) {
    asm volatile("st.shared.v2.b32 [%0], {%1,%2};" :: "r"(a), "r"(x), "r"(y) : "memory");
}

#define S2_FETCHB(S, koB) do {                                                     \
    uint32_t r_[4];                                                                \
    ldx4t(r_, bA[0] + (koB)); b0##S[0]=r_[0]; b1##S[0]=r_[1]; b0##S[1]=r_[2]; b1##S[1]=r_[3]; \
    ldx4t(r_, bA[1] + (koB)); b0##S[2]=r_[0]; b1##S[2]=r_[1]; b0##S[3]=r_[2]; b1##S[3]=r_[3]; \
    ldx4t(r_, bA[2] + (koB)); b0##S[4]=r_[0]; b1##S[4]=r_[1]; b0##S[5]=r_[2]; b1##S[5]=r_[3]; \
    { uint32_t r2_[2]; ldx2t(r2_, bA[3] + (koB)); b0##S[6]=r2_[0]; b1##S[6]=r2_[1]; } \
} while (0)

// ------------------------------------------------------------------ init
__global__ void init_kernel() {
    int idx = blockIdx.x * blockDim.x + threadIdx.x;
    if (idx < 448) {
        int t = (idx < 224) ? idx : (idx - 224 + 1);
        float c = 0.f;
        if (t < 224) {
            int i2 = t % 112;
            int d = 2 * i2 + 1;
            float th = 3.14159265358979323846f * (float)d / 224.0f;
            float eps = (i2 & 1) ? -1.0f : 1.0f;
            c = eps * (cosf(th) / sinf(th)) / 224.0f;
        }
        g_strip[idx] = __float2half_rn(c);
    }
}

// ------------------------------------------------------------------ fused
// smem: A0 26880 | A1 26880 | To' 26880 | Tec 26880 | strip 896 | red 32
__global__ __launch_bounds__(256, 2) void fused_kernel(const float* __restrict__ x,
                                                       float* __restrict__ out) {
    extern __shared__ char sm[];
    const uint32_t SA0 = 0, SA1 = 26880, STo = 53760, STec = 80640,
                   SSTRIP = 107520, SRED = 108416;
    uint32_t sb = smem_u32(sm);
    int tid = threadIdx.x, wid = tid >> 5, lane = tid & 31;
    int img = blockIdx.x;
    const float* xim = x + (size_t)img * 224 * 224;

    // strip -> smem
    {
        const uint32_t* gs = (const uint32_t*)g_strip;
        for (int i = tid; i < 224; i += 256)
            *(uint32_t*)(sm + SSTRIP + i * 4) = gs[i];
    }

    int wm = wid & 3, wn = wid >> 2, nbase = wn * 56;
    int mb0 = wm * 16, mb1 = (wm < 3) ? (mb0 + 64) : 96;

    const uint32_t* stripw =
        (const uint32_t*)(sm + SSTRIP + (((lane >> 2) & 1) ? 448 : 0));
    int lterm = (lane >> 2) + ((lane & 3) << 1);

    float csum = 0.f;

    // ---- load half-0 into A0 (blocking) ----
    {
        const float4* xr = (const float4*)xim;
        for (int i = tid; i < 3136; i += 256) {
            int r = i / 28, t2 = i - r * 28;
            const float4* p = xr + (size_t)r * 56 + 2 * t2;
            float4 v0 = p[0], v1 = p[1];
            sts64(sb + SA0 + r * PADB + (216 - 8 * t2),
                  pk2(v1.w, v1.y), pk2(v0.w, v0.y));
            if (r & 1) {
                float t = v0.y - v0.w + v1.y - v1.w;
                csum += ((r >> 1) & 1) ? -t : t;
            }
        }
    }
    __syncthreads();

    // ================= GEMM half-0 (A0) + pipelined load half-1 -> A1 ======
    {
        uint32_t aoff = (uint32_t)((lane & 15) * PADB + (lane >> 4) * 16);
        uint32_t aA0 = sb + SA0 + mb0 * PADB + aoff;
        uint32_t aA1 = sb + SA0 + mb1 * PADB + aoff;

        float acc[2][7][4];
        #pragma unroll
        for (int mt = 0; mt < 2; mt++)
            #pragma unroll
            for (int nt = 0; nt < 7; nt++)
                #pragma unroll
                for (int q = 0; q < 4; q++) acc[mt][nt][q] = 0.f;

        // pipelined-load state (half-1, rows 112..223)
        const float4* xr1 = (const float4*)(xim + 112 * 224);
        int i0 = tid, i1 = tid + 256, inext = tid + 512;
        float4 c0a, c0b, c1a, c1b;
        if (i0 < 3136) {
            int r = i0 / 28, t2 = i0 - r * 28;
            const float4* p = xr1 + (size_t)r * 56 + 2 * t2;
            c0a = p[0]; c0b = p[1];
        }
        if (i1 < 3136) {
            int r = i1 / 28, t2 = i1 - r * 28;
            const float4* p = xr1 + (size_t)r * 56 + 2 * t2;
            c1a = p[0]; c1b = p[1];
        }

        int wq = (nbase + lterm) >> 1;
        uint32_t a0X[4], a1X[4], a0Y[4], a1Y[4];
        ldx4(a0X, aA0); ldx4(a1X, aA1);
        #pragma unroll
        for (int kk = 0; kk < 7; kk++) {
            uint32_t L[8];
            #pragma unroll
            for (int q = 0; q < 8; q++) L[q] = stripw[wq + 8 * kk + 4 * q];
            if (kk < 6) {
                uint32_t ko = (uint32_t)(kk + 1) * 32;
                if (kk & 1) { ldx4(a0X, aA0 + ko); ldx4(a1X, aA1 + ko); }
                else        { ldx4(a0Y, aA0 + ko); ldx4(a1Y, aA1 + ko); }
            }
            const uint32_t* a0c = (kk & 1) ? a0Y : a0X;
            const uint32_t* a1c = (kk & 1) ? a1Y : a1X;
            #pragma unroll
            for (int nt = 0; nt < 7; nt++) {
                mma16816(acc[0][nt], a0c, L[nt], L[nt + 1]);
                mma16816(acc[1][nt], a1c, L[nt], L[nt + 1]);
            }
            // ---- pipelined load, slot 0: store pending, fetch +2 ahead ----
            if (i0 < 3136) {
                int r = i0 / 28, t2 = i0 - r * 28;
                sts64(sb + SA1 + r * PADB + (216 - 8 * t2),
                      pk2(c0b.w, c0b.y), pk2(c0a.w, c0a.y));
                if (r & 1) {   // a = 56 + (r>>1); 56 even -> same sign rule as half-0
                    float t = c0a.y - c0a.w + c0b.y - c0b.w;
                    csum += ((r >> 1) & 1) ? -t : t;
                }
            }
            i0 = inext; inext += 256;
            if (i0 < 3136) {
                int r = i0 / 28, t2 = i0 - r * 28;
                const float4* p = xr1 + (size_t)r * 56 + 2 * t2;
                c0a = p[0]; c0b = p[1];
            }
            // ---- slot 1 ----
            if (i1 < 3136) {
                int r = i1 / 28, t2 = i1 - r * 28;
                sts64(sb + SA1 + r * PADB + (216 - 8 * t2),
                      pk2(c1b.w, c1b.y), pk2(c1a.w, c1a.y));
                if (r & 1) {
                    float t = c1a.y - c1a.w + c1b.y - c1b.w;
                    csum += ((r >> 1) & 1) ? -t : t;
                }
            }
            i1 = inext; inext += 256;
            if (i1 < 3136) {
                int r = i1 / 28, t2 = i1 - r * 28;
                const float4* p = xr1 + (size_t)r * 56 + 2 * t2;
                c1a = p[0]; c1b = p[1];
            }
        }

        // epilogue half-0: odd rows add 0.5*x[h][2n] (L2-hot) -> To'; even -> Tec
        #pragma unroll
        for (int mt = 0; mt < 2; mt++) {
            if (mt == 1 && wm == 3) break;
            int mb = mt ? mb1 : mb0;
            int rlo = mb + (lane >> 2), rhi = rlo + 8;   // same parity
            int odd = rlo & 1;
            #pragma unroll
            for (int nt = 0; nt < 7; nt++) {
                int n = nbase + nt * 8 + 2 * (lane & 3);
                float v0 = acc[mt][nt][0], v1 = acc[mt][nt][1];
                float v2 = acc[mt][nt][2], v3 = acc[mt][nt][3];
                if (odd) {
                    float4 e0 = __ldg((const float4*)(xim + (size_t)rlo * 224 + 2 * n));
                    float4 e1 = __ldg((const float4*)(xim + (size_t)rhi * 224 + 2 * n));
                    v0 += 0.5f * e0.x; v1 += 0.5f * e0.z;
                    v2 += 0.5f * e1.x; v3 += 0.5f * e1.z;
                }
                uint32_t plo = pk2(v0, v1), phi = pk2(v2, v3);
                #pragma unroll
                for (int hf = 0; hf < 2; hf++) {
                    int h = hf ? rhi : rlo;          // hbase = 0
                    uint32_t pv = hf ? phi : plo;
                    int q = h >> 1;
                    if (odd)
                        *(uint32_t*)(sm + STo + (111 - q) * PADB + 2 * n) = pv;
                    else
                        *(uint32_t*)(sm + STec + q * PADB + 2 * n) = pv;
                }
            }
        }
    }
    __syncthreads();   // A1 complete, To/Tec(h0) published

    // ================= GEMM half-1 (A1) ================================
    {
        uint32_t aoff = (uint32_t)((lane & 15) * PADB + (lane >> 4) * 16);
        uint32_t aA0 = sb + SA1 + mb0 * PADB + aoff;
        uint32_t aA1 = sb + SA1 + mb1 * PADB + aoff;

        float acc[2][7][4];
        #pragma unroll
        for (int mt = 0; mt < 2; mt++)
            #pragma unroll
            for (int nt = 0; nt < 7; nt++)
                #pragma unroll
                for (int q = 0; q < 4; q++) acc[mt][nt][q] = 0.f;

        int wq = (nbase + lterm) >> 1;
        uint32_t a0X[4], a1X[4], a0Y[4], a1Y[4];
        ldx4(a0X, aA0); ldx4(a1X, aA1);
        #pragma unroll
        for (int kk = 0; kk < 7; kk++) {
            uint32_t L[8];
            #pragma unroll
            for (int q = 0; q < 8; q++) L[q] = stripw[wq + 8 * kk + 4 * q];
            if (kk < 6) {
                uint32_t ko = (uint32_t)(kk + 1) * 32;
                if (kk & 1) { ldx4(a0X, aA0 + ko); ldx4(a1X, aA1 + ko); }
                else        { ldx4(a0Y, aA0 + ko); ldx4(a1Y, aA1 + ko); }
            }
            const uint32_t* a0c = (kk & 1) ? a0Y : a0X;
            const uint32_t* a1c = (kk & 1) ? a1Y : a1X;
            #pragma unroll
            for (int nt = 0; nt < 7; nt++) {
                mma16816(acc[0][nt], a0c, L[nt], L[nt + 1]);
                mma16816(acc[1][nt], a1c, L[nt], L[nt + 1]);
            }
        }

        // epilogue half-1: same routing, rows h = 112 + r
        #pragma unroll
        for (int mt = 0; mt < 2; mt++) {
            if (mt == 1 && wm == 3) break;
            int mb = mt ? mb1 : mb0;
            int rlo = mb + (lane >> 2), rhi = rlo + 8;
            int odd = rlo & 1;                            // h parity = r parity
            #pragma unroll
            for (int nt = 0; nt < 7; nt++) {
                int n = nbase + nt * 8 + 2 * (lane & 3);
                float v0 = acc[mt][nt][0], v1 = acc[mt][nt][1];
                float v2 = acc[mt][nt][2], v3 = acc[mt][nt][3];
                if (odd) {
                    float4 e0 = __ldg((const float4*)(xim + (size_t)(112 + rlo) * 224 + 2 * n));
                    float4 e1 = __ldg((const float4*)(xim + (size_t)(112 + rhi) * 224 + 2 * n));
                    v0 += 0.5f * e0.x; v1 += 0.5f * e0.z;
                    v2 += 0.5f * e1.x; v3 += 0.5f * e1.z;
                }
                uint32_t plo = pk2(v0, v1), phi = pk2(v2, v3);
                #pragma unroll
                for (int hf = 0; hf < 2; hf++) {
                    int h = 112 + (hf ? rhi : rlo);
                    uint32_t pv = hf ? phi : plo;
                    int q = h >> 1;
                    if (odd)
                        *(uint32_t*)(sm + STo + (111 - q) * PADB + 2 * n) = pv;
                    else
                        *(uint32_t*)(sm + STec + q * PADB + 2 * n) = pv;
                }
            }
        }
    }

    // C reduction -> corr
    #pragma unroll
    for (int o = 16; o; o >>= 1) csum += __shfl_down_sync(0xffffffffu, csum, o);
    if (lane == 0) ((float*)(sm + SRED))[wid] = csum;
    __syncthreads();   // publishes To/Tec(h1)
    float corr;
    {
        float s = 0.f;
        #pragma unroll
        for (int i = 0; i < 8; i++) s += ((float*)(sm + SRED))[i];
        corr = s * (1.0f / 50176.0f);
    }

    // ================= stage 2 =========================================
    {
        uint32_t bA[4];
        #pragma unroll
        for (int p = 0; p < 3; p++) {
            int j = (lane & 7) + ((lane & 8) ? 8 : 0);
            int n = nbase + p * 16 + ((lane & 16) ? 8 : 0);
            bA[p] = sb + STo + j * PADB + n * 2;
        }
        {
            int j = lane & 15;
            bA[3] = sb + STo + j * PADB + (nbase + 48) * 2;
        }

        float acc[2][7][4];
        #pragma unroll
        for (int mt = 0; mt < 2; mt++)
            #pragma unroll
            for (int nt = 0; nt < 7; nt++)
                #pragma unroll
                for (int q = 0; q < 4; q++) acc[mt][nt][q] = 0.f;

        int wq0 = (mb0 + lterm) >> 1;
        int wq1 = wq0 + ((mb1 - mb0) >> 1);

        uint32_t b0X[7], b1X[7], b0Y[7], b1Y[7];
        S2_FETCHB(X, 0);
        #pragma unroll
        for (int kk = 0; kk < 7; kk++) {
            uint32_t A0a = stripw[wq0 + 8 * kk];
            uint32_t A1a = stripw[wq0 + 8 * kk + 4];
            uint32_t A3a = stripw[wq0 + 8 * kk + 8];
            uint32_t A0b = stripw[wq1 + 8 * kk];
            uint32_t A1b = stripw[wq1 + 8 * kk + 4];
            uint32_t A3b = stripw[wq1 + 8 * kk + 8];
            uint32_t am0[4] = {A0a, A1a, A1a, A3a};
            uint32_t am1[4] = {A0b, A1b, A1b, A3b};
            if (kk < 6) {
                uint32_t koB = (uint32_t)(kk + 1) * 16 * PADB;
                if (kk & 1) { S2_FETCHB(X, koB); }
                else        { S2_FETCHB(Y, koB); }
            }
            const uint32_t* b0c = (kk & 1) ? b0Y : b0X;
            const uint32_t* b1c = (kk & 1) ? b1Y : b1X;
            #pragma unroll
            for (int nt = 0; nt < 7; nt++) {
                mma16816(acc[0][nt], am0, b0c[nt], b1c[nt]);
                mma16816(acc[1][nt], am1, b0c[nt], b1c[nt]);
            }
        }

        // epilogue: + 0.5*Tec + 0.25*x[2m][2n] (L2) - sign*corr
        #pragma unroll
        for (int mt = 0; mt < 2; mt++) {
            if (mt == 1 && wm == 3) break;
            int mb = mt ? mb1 : mb0;
            int mlo = mb + (lane >> 2), mhi = mlo + 8;
            #pragma unroll
            for (int nt = 0; nt < 7; nt++) {
                int n = nbase + nt * 8 + 2 * (lane & 3);
                #pragma unroll
                for (int hf = 0; hf < 2; hf++) {
                    int m = hf ? mhi : mlo;
                    uint32_t tp = *(const uint32_t*)(sm + STec + m * PADB + 2 * n);
                    __half2 th = *reinterpret_cast<__half2*>(&tp);
                    float4 xe = __ldg((const float4*)(xim + (size_t)(2 * m) * 224 + 2 * n));
                    float v0 = acc[mt][nt][hf ? 2 : 0] + 0.5f * __half2float(th.x)
                             + 0.25f * xe.x;
                    float v1 = acc[mt][nt][hf ? 3 : 1] + 0.5f * __half2float(th.y)
                             + 0.25f * xe.z;
                    v0 -= ((m + n) & 1) ? -corr : corr;
                    v1 -= ((m + n + 1) & 1) ? -corr : corr;
                    *(float2*)&out[(size_t)img * HO * HO + (size_t)m * HO + n] =
                        make_float2(v0, v1);
                }
            }
        }
    }
}

// ------------------------------------------------------------------ launch
extern "C" void kernel_launch(void* const* d_in, const int* in_sizes, int n_in,
                              void* d_out, int out_size) {
    (void)in_sizes; (void)n_in; (void)out_size;
    const float* x = (const float*)d_in[0];
    float* out = (float*)d_out;

    cudaFuncSetAttribute(fused_kernel,
                         cudaFuncAttributeMaxDynamicSharedMemorySize, 108448);

    init_kernel<<<2, 256>>>();
    fused_kernel<<<NIMG, 256, 108448>>>(x, out);
}

// round 17
// speedup vs baseline: 1.2237x; 1.2237x over previous
#include <cuda_runtime.h>
#include <cuda_fp16.h>
#include <cstdint>
#include <math.h>

// FLC pooling, fused, circulant-strip + deferred-diagonal edition. 1 CTA = 1 image.
//   Conv[h][n] = sum_j x[h][2j+1] * R[n][j]   (R circulant -> 448B strip)
//   To[j][n]  = 0.5*x[2j+1][2n] + Conv[2j+1][n]   (stored reversed; full odd-row T)
//   Tec[q][n] = Conv[2q][n]                        (even diagonal deferred)
//   out[m][n] = 0.25*x[2m][2n] + 0.5*Tec[m][n] + sum_j R[m][j] To[j][n]
//               - (-1)^(m+n) * C_img / 224^2
// Blocking loads (R12 phase structure — no in-loop pipelining; reg-pressure safe).

#define HO   112
#define NIMG 1024
#define PADB 240          // smem row stride bytes -> conflict-free ldmatrix

__device__ __half g_strip[448];   // [0..223]=v2[t]; [224+i]=v2[i+1] (parity copy)

// ------------------------------------------------------------------ helpers
__device__ __forceinline__ uint32_t smem_u32(const void* p) {
    uint32_t a;
    asm("{ .reg .u64 t; cvta.to.shared.u64 t, %1; cvt.u32.u64 %0, t; }"
        : "=r"(a) : "l"(p));
    return a;
}
__device__ __forceinline__ void ldx4(uint32_t r[4], uint32_t a) {
    asm volatile("ldmatrix.sync.aligned.m8n8.x4.shared.b16 {%0,%1,%2,%3}, [%4];"
                 : "=r"(r[0]), "=r"(r[1]), "=r"(r[2]), "=r"(r[3]) : "r"(a));
}
__device__ __forceinline__ void ldx4t(uint32_t r[4], uint32_t a) {
    asm volatile("ldmatrix.sync.aligned.m8n8.x4.trans.shared.b16 {%0,%1,%2,%3}, [%4];"
                 : "=r"(r[0]), "=r"(r[1]), "=r"(r[2]), "=r"(r[3]) : "r"(a));
}
__device__ __forceinline__ void ldx2t(uint32_t r[2], uint32_t a) {
    asm volatile("ldmatrix.sync.aligned.m8n8.x2.trans.shared.b16 {%0,%1}, [%2];"
                 : "=r"(r[0]), "=r"(r[1]) : "r"(a));
}
__device__ __forceinline__ void mma16816(float c[4], const uint32_t a[4],
                                         uint32_t b0, uint32_t b1) {
    asm volatile(
        "mma.sync.aligned.m16n8k16.row.col.f32.f16.f16.f32 "
        "{%0,%1,%2,%3}, {%4,%5,%6,%7}, {%8,%9}, {%0,%1,%2,%3};"
        : "+f"(c[0]), "+f"(c[1]), "+f"(c[2]), "+f"(c[3])
        : "r"(a[0]), "r"(a[1]), "r"(a[2]), "r"(a[3]), "r"(b0), "r"(b1));
}
__device__ __forceinline__ uint32_t pk2(float a, float b) {
    __half2 h = __floats2half2_rn(a, b);
    return *reinterpret_cast<uint32_t*>(&h);
}
__device__ __forceinline__ void sts64(uint32_t a, uint32_t x, uint32_t y) {
    asm volatile("st.shared.v2.b32 [%0], {%1,%2};" :: "r"(a), "r"(x), "r"(y) : "memory");
}

#define S2_FETCHB(S, koB) do {                                                     \
    uint32_t r_[4];                                                                \
    ldx4t(r_, bA[0] + (koB)); b0##S[0]=r_[0]; b1##S[0]=r_[1]; b0##S[1]=r_[2]; b1##S[1]=r_[3]; \
    ldx4t(r_, bA[1] + (koB)); b0##S[2]=r_[0]; b1##S[2]=r_[1]; b0##S[3]=r_[2]; b1##S[3]=r_[3]; \
    ldx4t(r_, bA[2] + (koB)); b0##S[4]=r_[0]; b1##S[4]=r_[1]; b0##S[5]=r_[2]; b1##S[5]=r_[3]; \
    { uint32_t r2_[2]; ldx2t(r2_, bA[3] + (koB)); b0##S[6]=r2_[0]; b1##S[6]=r2_[1]; } \
} while (0)

// ------------------------------------------------------------------ init
__global__ void init_kernel() {
    int idx = blockIdx.x * blockDim.x + threadIdx.x;
    if (idx < 448) {
        int t = (idx < 224) ? idx : (idx - 224 + 1);
        float c = 0.f;
        if (t < 224) {
            int i2 = t % 112;
            int d = 2 * i2 + 1;
            float th = 3.14159265358979323846f * (float)d / 224.0f;
            float eps = (i2 & 1) ? -1.0f : 1.0f;
            c = eps * (cosf(th) / sinf(th)) / 224.0f;
        }
        g_strip[idx] = __float2half_rn(c);
    }
}

// ------------------------------------------------------------------ fused
// smem: A 26880 | To' 26880 | Tec 26880 | strip 896 | red 32  = 81568 B
__global__ __launch_bounds__(256, 2) void fused_kernel(const float* __restrict__ x,
                                                       float* __restrict__ out) {
    extern __shared__ char sm[];
    const uint32_t SA = 0, STo = 26880, STec = 53760,
                   SSTRIP = 80640, SRED = 81536;
    uint32_t sb = smem_u32(sm);
    int tid = threadIdx.x, wid = tid >> 5, lane = tid & 31;
    int img = blockIdx.x;
    const float* xim = x + (size_t)img * 224 * 224;

    // strip -> smem
    {
        const uint32_t* gs = (const uint32_t*)g_strip;
        for (int i = tid; i < 224; i += 256)
            *(uint32_t*)(sm + SSTRIP + i * 4) = gs[i];
    }

    int wm = wid & 3, wn = wid >> 2, nbase = wn * 56;
    int mb0 = wm * 16, mb1 = (wm < 3) ? (mb0 + 64) : 96;

    const uint32_t* stripw =
        (const uint32_t*)(sm + SSTRIP + (((lane >> 2) & 1) ? 448 : 0));
    int lterm = (lane >> 2) + ((lane & 3) << 1);

    float csum = 0.f;

    // ================= stage 1: two 112-row halves ======================
    #pragma unroll 1
    for (int half = 0; half < 2; half++) {
        int hbase = half * HO;
        if (half) __syncthreads();   // A reuse: all prior ldmatrix reads done

        // x half, odd cols reversed -> fp16 A; fused C partial-reduction
        {
            const float4* xr = (const float4*)(xim + (size_t)hbase * 224);
            for (int i = tid; i < 3136; i += 256) {
                int r = i / 28, t2 = i - r * 28;
                const float4* p = xr + (size_t)r * 56 + 2 * t2;
                float4 v0 = p[0], v1 = p[1];
                sts64(sb + SA + r * PADB + (216 - 8 * t2),
                      pk2(v1.w, v1.y), pk2(v0.w, v0.y));
                if (r & 1) {   // a = hbase/2 + (r>>1); hbase/2 even both halves
                    float t = v0.y - v0.w + v1.y - v1.w;
                    csum += ((r >> 1) & 1) ? -t : t;
                }
            }
        }
        __syncthreads();

        uint32_t aoff = (uint32_t)((lane & 15) * PADB + (lane >> 4) * 16);
        uint32_t aA0 = sb + SA + mb0 * PADB + aoff;
        uint32_t aA1 = sb + SA + mb1 * PADB + aoff;

        float acc[2][7][4];
        #pragma unroll
        for (int mt = 0; mt < 2; mt++)
            #pragma unroll
            for (int nt = 0; nt < 7; nt++)
                #pragma unroll
                for (int q = 0; q < 4; q++) acc[mt][nt][q] = 0.f;

        int wq = (nbase + lterm) >> 1;
        uint32_t a0X[4], a1X[4], a0Y[4], a1Y[4];
        ldx4(a0X, aA0); ldx4(a1X, aA1);
        #pragma unroll
        for (int kk = 0; kk < 7; kk++) {
            uint32_t L[8];
            #pragma unroll
            for (int q = 0; q < 8; q++) L[q] = stripw[wq + 8 * kk + 4 * q];
            if (kk < 6) {
                uint32_t ko = (uint32_t)(kk + 1) * 32;
                if (kk & 1) { ldx4(a0X, aA0 + ko); ldx4(a1X, aA1 + ko); }
                else        { ldx4(a0Y, aA0 + ko); ldx4(a1Y, aA1 + ko); }
            }
            const uint32_t* a0c = (kk & 1) ? a0Y : a0X;
            const uint32_t* a1c = (kk & 1) ? a1Y : a1X;
            #pragma unroll
            for (int nt = 0; nt < 7; nt++) {
                mma16816(acc[0][nt], a0c, L[nt], L[nt + 1]);
                mma16816(acc[1][nt], a1c, L[nt], L[nt + 1]);
            }
        }

        // epilogue: odd rows add 0.5*x[h][2n] (L2-hot) -> To'; even rows -> Tec
        #pragma unroll
        for (int mt = 0; mt < 2; mt++) {
            if (mt == 1 && wm == 3) break;
            int mb = mt ? mb1 : mb0;
            int rlo = mb + (lane >> 2), rhi = rlo + 8;   // same parity
            int odd = rlo & 1;
            #pragma unroll
            for (int nt = 0; nt < 7; nt++) {
                int n = nbase + nt * 8 + 2 * (lane & 3);
                float v0 = acc[mt][nt][0], v1 = acc[mt][nt][1];
                float v2 = acc[mt][nt][2], v3 = acc[mt][nt][3];
                if (odd) {
                    float4 e0 = __ldg((const float4*)(xim + (size_t)(hbase + rlo) * 224 + 2 * n));
                    float4 e1 = __ldg((const float4*)(xim + (size_t)(hbase + rhi) * 224 + 2 * n));
                    v0 += 0.5f * e0.x; v1 += 0.5f * e0.z;
                    v2 += 0.5f * e1.x; v3 += 0.5f * e1.z;
                }
                uint32_t plo = pk2(v0, v1), phi = pk2(v2, v3);
                #pragma unroll
                for (int hf = 0; hf < 2; hf++) {
                    int h = hbase + (hf ? rhi : rlo);
                    uint32_t pv = hf ? phi : plo;
                    int q = h >> 1;
                    if (odd)
                        *(uint32_t*)(sm + STo + (111 - q) * PADB + 2 * n) = pv;
                    else
                        *(uint32_t*)(sm + STec + q * PADB + 2 * n) = pv;
                }
            }
        }
    }

    // C reduction -> corr
    #pragma unroll
    for (int o = 16; o; o >>= 1) csum += __shfl_down_sync(0xffffffffu, csum, o);
    if (lane == 0) ((float*)(sm + SRED))[wid] = csum;
    __syncthreads();   // publishes To'/Tec
    float corr;
    {
        float s = 0.f;
        #pragma unroll
        for (int i = 0; i < 8; i++) s += ((float*)(sm + SRED))[i];
        corr = s * (1.0f / 50176.0f);
    }

    // ================= stage 2 =========================================
    {
        uint32_t bA[4];
        #pragma unroll
        for (int p = 0; p < 3; p++) {
            int j = (lane & 7) + ((lane & 8) ? 8 : 0);
            int n = nbase + p * 16 + ((lane & 16) ? 8 : 0);
            bA[p] = sb + STo + j * PADB + n * 2;
        }
        {
            int j = lane & 15;
            bA[3] = sb + STo + j * PADB + (nbase + 48) * 2;
        }

        float acc[2][7][4];
        #pragma unroll
        for (int mt = 0; mt < 2; mt++)
            #pragma unroll
            for (int nt = 0; nt < 7; nt++)
                #pragma unroll
                for (int q = 0; q < 4; q++) acc[mt][nt][q] = 0.f;

        int wq0 = (mb0 + lterm) >> 1;
        int wq1 = wq0 + ((mb1 - mb0) >> 1);

        uint32_t b0X[7], b1X[7], b0Y[7], b1Y[7];
        S2_FETCHB(X, 0);
        #pragma unroll
        for (int kk = 0; kk < 7; kk++) {
            uint32_t A0a = stripw[wq0 + 8 * kk];
            uint32_t A1a = stripw[wq0 + 8 * kk + 4];
            uint32_t A3a = stripw[wq0 + 8 * kk + 8];
            uint32_t A0b = stripw[wq1 + 8 * kk];
            uint32_t A1b = stripw[wq1 + 8 * kk + 4];
            uint32_t A3b = stripw[wq1 + 8 * kk + 8];
            uint32_t am0[4] = {A0a, A1a, A1a, A3a};
            uint32_t am1[4] = {A0b, A1b, A1b, A3b};
            if (kk < 6) {
                uint32_t koB = (uint32_t)(kk + 1) * 16 * PADB;
                if (kk & 1) { S2_FETCHB(X, koB); }
                else        { S2_FETCHB(Y, koB); }
            }
            const uint32_t* b0c = (kk & 1) ? b0Y : b0X;
            const uint32_t* b1c = (kk & 1) ? b1Y : b1X;
            #pragma unroll
            for (int nt = 0; nt < 7; nt++) {
                mma16816(acc[0][nt], am0, b0c[nt], b1c[nt]);
                mma16816(acc[1][nt], am1, b0c[nt], b1c[nt]);
            }
        }

        // epilogue: + 0.5*Tec + 0.25*x[2m][2n] (L2) - sign*corr
        #pragma unroll
        for (int mt = 0; mt < 2; mt++) {
            if (mt == 1 && wm == 3) break;
            int mb = mt ? mb1 : mb0;
            int mlo = mb + (lane >> 2), mhi = mlo + 8;
            #pragma unroll
            for (int nt = 0; nt < 7; nt++) {
                int n = nbase + nt * 8 + 2 * (lane & 3);
                #pragma unroll
                for (int hf = 0; hf < 2; hf++) {
                    int m = hf ? mhi : mlo;
                    uint32_t tp = *(const uint32_t*)(sm + STec + m * PADB + 2 * n);
                    __half2 th = *reinterpret_cast<__half2*>(&tp);
                    float4 xe = __ldg((const float4*)(xim + (size_t)(2 * m) * 224 + 2 * n));
                    float v0 = acc[mt][nt][hf ? 2 : 0] + 0.5f * __half2float(th.x)
                             + 0.25f * xe.x;
                    float v1 = acc[mt][nt][hf ? 3 : 1] + 0.5f * __half2float(th.y)
                             + 0.25f * xe.z;
                    v0 -= ((m + n) & 1) ? -corr : corr;
                    v1 -= ((m + n + 1) & 1) ? -corr : corr;
                    *(float2*)&out[(size_t)img * HO * HO + (size_t)m * HO + n] =
                        make_float2(v0, v1);
                }
            }
        }
    }
}

// ------------------------------------------------------------------ launch
extern "C" void kernel_launch(void* const* d_in, const int* in_sizes, int n_in,
                              void* d_out, int out_size) {
    (void)in_sizes; (void)n_in; (void)out_size;
    const float* x = (const float*)d_in[0];
    float* out = (float*)d_out;

    cudaFuncSetAttribute(fused_kernel,
                         cudaFuncAttributeMaxDynamicSharedMemorySize, 81568);

    init_kernel<<<2, 256>>>();
    fused_kernel<<<NIMG, 256, 81568>>>(x, out);
}